// round 1
// baseline (speedup 1.0000x reference)
#include <cuda_runtime.h>
#include <cuda_bf16.h>
#include <math.h>

#define N_NODES 50000
#define N_EDGES 600000
#define DF 128          // feature dim
#define KTOT 256        // concatenated K = [agg | x]

// ---------------- scratch (device globals; no allocation) ----------------
__device__ float g_agg[(size_t)N_NODES * DF];
__device__ float g_buf0[(size_t)N_NODES * DF];
__device__ float g_buf1[(size_t)N_NODES * DF];
__device__ int   g_counts[N_NODES + 1];
__device__ int   g_offsets[N_NODES + 1];
__device__ int   g_cursor[N_NODES];
__device__ int   g_src_sorted[N_EDGES];
__device__ float g_B1[KTOT * DF];   // [W1; R1]
__device__ float g_B2[KTOT * DF];   // [W2; R2]

// ---------------- f32x2 helpers ----------------
__device__ __forceinline__ unsigned long long pack2(float lo, float hi) {
    unsigned long long r;
    asm("mov.b64 %0, {%1, %2};" : "=l"(r) : "f"(lo), "f"(hi));
    return r;
}
__device__ __forceinline__ void unpack2(unsigned long long v, float& lo, float& hi) {
    asm("mov.b64 {%0, %1}, %2;" : "=f"(lo), "=f"(hi) : "l"(v));
}
__device__ __forceinline__ void fma2(unsigned long long& d, unsigned long long a,
                                     unsigned long long b) {
    asm("fma.rn.f32x2 %0, %1, %2, %0;" : "+l"(d) : "l"(a), "l"(b));
}

// ---------------- preprocessing ----------------
__global__ void zero_counts_kernel() {
    int i = blockIdx.x * blockDim.x + threadIdx.x;
    if (i <= N_NODES) g_counts[i] = 0;
}

__global__ void hist_kernel(const int* __restrict__ dst) {
    int i = blockIdx.x * blockDim.x + threadIdx.x;
    if (i < N_EDGES) atomicAdd(&g_counts[dst[i]], 1);
}

// single-block exclusive scan of counts -> offsets (+ cursor copy)
__global__ void scan_kernel() {
    __shared__ int wsum[32];
    __shared__ int s_carry;
    const int tid = threadIdx.x, lane = tid & 31, wid = tid >> 5;
    if (tid == 0) s_carry = 0;
    __syncthreads();
    for (int base = 0; base < N_NODES; base += 1024) {
        int carry = s_carry;
        int i = base + tid;
        int v = (i < N_NODES) ? g_counts[i] : 0;
        int x = v;
        #pragma unroll
        for (int o = 1; o < 32; o <<= 1) {
            int y = __shfl_up_sync(0xffffffffu, x, o);
            if (lane >= o) x += y;
        }
        if (lane == 31) wsum[wid] = x;
        __syncthreads();
        if (wid == 0) {
            int w = wsum[lane];
            #pragma unroll
            for (int o = 1; o < 32; o <<= 1) {
                int y = __shfl_up_sync(0xffffffffu, w, o);
                if (lane >= o) w += y;
            }
            wsum[lane] = w;
        }
        __syncthreads();
        int incl = x + (wid > 0 ? wsum[wid - 1] : 0) + carry;
        if (i < N_NODES) {
            int excl = incl - v;
            g_offsets[i] = excl;
            g_cursor[i]  = excl;
            if (i == N_NODES - 1) g_offsets[N_NODES] = incl;
        }
        __syncthreads();
        if (tid == 0) s_carry = carry + wsum[31];
        __syncthreads();
    }
}

__global__ void scatter_kernel(const int* __restrict__ src, const int* __restrict__ dst) {
    int i = blockIdx.x * blockDim.x + threadIdx.x;
    if (i < N_EDGES) {
        int d = dst[i];
        int p = atomicAdd(&g_cursor[d], 1);
        g_src_sorted[p] = src[i];
    }
}

__global__ void buildB_kernel(const float* __restrict__ W1, const float* __restrict__ R1,
                              const float* __restrict__ W2, const float* __restrict__ R2) {
    int i = blockIdx.x * blockDim.x + threadIdx.x;
    if (i < DF * DF) {
        g_B1[i]           = W1[i];
        g_B1[DF * DF + i] = R1[i];
        g_B2[i]           = W2[i];
        g_B2[DF * DF + i] = R2[i];
    }
}

// ---------------- aggregation: one warp per node, CSR max-reduce ----------------
__global__ void agg_kernel(const float* __restrict__ h) {
    const int gw   = (blockIdx.x * blockDim.x + threadIdx.x) >> 5;
    const int lane = threadIdx.x & 31;
    if (gw >= N_NODES) return;
    const int beg = g_offsets[gw];
    const int end = g_offsets[gw + 1];

    float4 acc;
    acc.x = acc.y = acc.z = acc.w = -INFINITY;

    for (int j = beg; j < end; j += 32) {
        int idx = 0;
        if (j + lane < end) idx = g_src_sorted[j + lane];
        int cnt = end - j;
        if (cnt > 32) cnt = 32;
        int i = 0;
        // 4-deep software pipeline for MLP
        for (; i + 4 <= cnt; i += 4) {
            int s0 = __shfl_sync(0xffffffffu, idx, i + 0);
            int s1 = __shfl_sync(0xffffffffu, idx, i + 1);
            int s2 = __shfl_sync(0xffffffffu, idx, i + 2);
            int s3 = __shfl_sync(0xffffffffu, idx, i + 3);
            float4 v0 = ((const float4*)(h + (size_t)s0 * DF))[lane];
            float4 v1 = ((const float4*)(h + (size_t)s1 * DF))[lane];
            float4 v2 = ((const float4*)(h + (size_t)s2 * DF))[lane];
            float4 v3 = ((const float4*)(h + (size_t)s3 * DF))[lane];
            v0.x = fmaxf(v0.x, v1.x); v0.y = fmaxf(v0.y, v1.y);
            v0.z = fmaxf(v0.z, v1.z); v0.w = fmaxf(v0.w, v1.w);
            v2.x = fmaxf(v2.x, v3.x); v2.y = fmaxf(v2.y, v3.y);
            v2.z = fmaxf(v2.z, v3.z); v2.w = fmaxf(v2.w, v3.w);
            acc.x = fmaxf(acc.x, fmaxf(v0.x, v2.x));
            acc.y = fmaxf(acc.y, fmaxf(v0.y, v2.y));
            acc.z = fmaxf(acc.z, fmaxf(v0.z, v2.z));
            acc.w = fmaxf(acc.w, fmaxf(v0.w, v2.w));
        }
        for (; i < cnt; i++) {
            int s = __shfl_sync(0xffffffffu, idx, i);
            float4 v = ((const float4*)(h + (size_t)s * DF))[lane];
            acc.x = fmaxf(acc.x, v.x); acc.y = fmaxf(acc.y, v.y);
            acc.z = fmaxf(acc.z, v.z); acc.w = fmaxf(acc.w, v.w);
        }
    }
    if (beg == end) { acc.x = acc.y = acc.z = acc.w = 0.0f; }  // isolated node -> 0
    ((float4*)(g_agg + (size_t)gw * DF))[lane] = acc;
}

// ---------------- GEMM: out = relu([agg|x] @ [W;R] + b) ----------------
// 128x128 tile, BK=16, 256 threads, 8x8 micro-tile (split 4+4), f32x2 FMAs.
#define GBM 128
#define GBN 128
#define GBK 16

__global__ __launch_bounds__(256, 2)
void gemm_kernel(const float* __restrict__ Aagg, const float* __restrict__ Ax,
                 const float* __restrict__ B, const float* __restrict__ bias,
                 float* __restrict__ out) {
    __shared__ float As[GBK][GBM + 4];   // +4 keeps 16B alignment of rows
    __shared__ float Bs[GBK][GBN];

    const int tid = threadIdx.x;
    const int tx  = tid & 15;   // output col group
    const int ty  = tid >> 4;   // output row group
    const int mb  = blockIdx.x * GBM;

    unsigned long long acc[8][4];
    #pragma unroll
    for (int r = 0; r < 8; r++)
        #pragma unroll
        for (int c = 0; c < 4; c++) acc[r][c] = 0ULL;

    for (int kt = 0; kt < KTOT; kt += GBK) {
        const float* Ap = (kt < DF) ? Aagg : Ax;
        const int kb = kt & (DF - 1);

        // A tile: 128 rows x 16 k (transposed into As[k][m])
        #pragma unroll
        for (int it = 0; it < 2; it++) {
            int i  = tid + it * 256;
            int ml = i >> 2;
            int kq = (i & 3) * 4;
            int row = mb + ml;
            float4 v = make_float4(0.f, 0.f, 0.f, 0.f);
            if (row < N_NODES)
                v = *(const float4*)(Ap + (size_t)row * DF + kb + kq);
            As[kq + 0][ml] = v.x;
            As[kq + 1][ml] = v.y;
            As[kq + 2][ml] = v.z;
            As[kq + 3][ml] = v.w;
        }
        // B tile: 16 k x 128 n
        #pragma unroll
        for (int it = 0; it < 2; it++) {
            int i  = tid + it * 256;
            int kr = i >> 5;
            int nq = (i & 31) * 4;
            *(float4*)&Bs[kr][nq] = *(const float4*)(B + (size_t)(kt + kr) * DF + nq);
        }
        __syncthreads();

        #pragma unroll
        for (int k = 0; k < GBK; k++) {
            float4 a0 = *(const float4*)&As[k][ty * 4];
            float4 a1 = *(const float4*)&As[k][64 + ty * 4];
            const unsigned long long* Bu = (const unsigned long long*)&Bs[k][0];
            unsigned long long b0 = Bu[tx * 2 + 0];
            unsigned long long b1 = Bu[tx * 2 + 1];
            unsigned long long b2 = Bu[32 + tx * 2 + 0];
            unsigned long long b3 = Bu[33 + tx * 2];
            float ar[8] = {a0.x, a0.y, a0.z, a0.w, a1.x, a1.y, a1.z, a1.w};
            #pragma unroll
            for (int r = 0; r < 8; r++) {
                unsigned long long ad = pack2(ar[r], ar[r]);
                fma2(acc[r][0], ad, b0);
                fma2(acc[r][1], ad, b1);
                fma2(acc[r][2], ad, b2);
                fma2(acc[r][3], ad, b3);
            }
        }
        __syncthreads();
    }

    // epilogue: + bias, relu, store
    float bn[8];
    #pragma unroll
    for (int c = 0; c < 4; c++) {
        bn[c]     = bias[tx * 4 + c];
        bn[4 + c] = bias[64 + tx * 4 + c];
    }
    #pragma unroll
    for (int r = 0; r < 8; r++) {
        int row = mb + ((r < 4) ? (ty * 4 + r) : (64 + ty * 4 + (r - 4)));
        if (row >= N_NODES) continue;
        float o[8];
        #pragma unroll
        for (int c = 0; c < 4; c++) {
            float lo, hi;
            unpack2(acc[r][c], lo, hi);
            o[c * 2] = lo; o[c * 2 + 1] = hi;
        }
        float4 o0 = make_float4(fmaxf(o[0] + bn[0], 0.f), fmaxf(o[1] + bn[1], 0.f),
                                fmaxf(o[2] + bn[2], 0.f), fmaxf(o[3] + bn[3], 0.f));
        float4 o1 = make_float4(fmaxf(o[4] + bn[4], 0.f), fmaxf(o[5] + bn[5], 0.f),
                                fmaxf(o[6] + bn[6], 0.f), fmaxf(o[7] + bn[7], 0.f));
        *(float4*)(out + (size_t)row * DF + tx * 4)      = o0;
        *(float4*)(out + (size_t)row * DF + 64 + tx * 4) = o1;
    }
}

// ---------------- launch ----------------
extern "C" void kernel_launch(void* const* d_in, const int* in_sizes, int n_in,
                              void* d_out, int out_size) {
    const float* x  = (const float*)d_in[0];
    const int*   ei = (const int*)d_in[1];
    const float* W1 = (const float*)d_in[2];
    const float* b1 = (const float*)d_in[3];
    const float* R1 = (const float*)d_in[4];
    const float* W2 = (const float*)d_in[5];
    const float* b2 = (const float*)d_in[6];
    const float* R2 = (const float*)d_in[7];
    float* out = (float*)d_out;

    const int* src = ei;
    const int* dst = ei + N_EDGES;

    float *p_buf0, *p_buf1, *p_agg, *p_B1, *p_B2;
    cudaGetSymbolAddress((void**)&p_buf0, g_buf0);
    cudaGetSymbolAddress((void**)&p_buf1, g_buf1);
    cudaGetSymbolAddress((void**)&p_agg,  g_agg);
    cudaGetSymbolAddress((void**)&p_B1,   g_B1);
    cudaGetSymbolAddress((void**)&p_B2,   g_B2);

    // preprocessing: CSR by dst
    zero_counts_kernel<<<(N_NODES + 256) / 256, 256>>>();
    hist_kernel<<<(N_EDGES + 255) / 256, 256>>>(dst);
    scan_kernel<<<1, 1024>>>();
    scatter_kernel<<<(N_EDGES + 255) / 256, 256>>>(src, dst);
    buildB_kernel<<<(DF * DF + 255) / 256, 256>>>(W1, R1, W2, R2);

    const int aggBlocks  = (N_NODES * 32 + 255) / 256;
    const int gemmBlocks = (N_NODES + GBM - 1) / GBM;

    // layer 1: x -> buf0
    agg_kernel<<<aggBlocks, 256>>>(x);
    gemm_kernel<<<gemmBlocks, 256>>>(p_agg, x, p_B1, b1, p_buf0);
    // layer 2: buf0 -> buf1
    agg_kernel<<<aggBlocks, 256>>>(p_buf0);
    gemm_kernel<<<gemmBlocks, 256>>>(p_agg, p_buf0, p_B2, b2, p_buf1);
    // layer 3: buf1 -> buf0
    agg_kernel<<<aggBlocks, 256>>>(p_buf1);
    gemm_kernel<<<gemmBlocks, 256>>>(p_agg, p_buf1, p_B2, b2, p_buf0);
    // layer 4: buf0 -> out
    agg_kernel<<<aggBlocks, 256>>>(p_buf0);
    gemm_kernel<<<gemmBlocks, 256>>>(p_agg, p_buf0, p_B2, b2, out);
}

// round 2
// speedup vs baseline: 1.2911x; 1.2911x over previous
#include <cuda_runtime.h>
#include <cuda_bf16.h>
#include <math.h>

#define N_NODES 50000
#define N_EDGES 600000
#define DF 128
#define KB3 768          // 3 * 256 split-bf16 K
#define NB_SCAN 49       // ceil(50000/1024)

typedef __nv_bfloat16 bf16;

// ---------------- scratch (device globals) ----------------
__device__ float g_h0[(size_t)N_NODES * DF];
__device__ float g_h1[(size_t)N_NODES * DF];
__device__ bf16  g_h0Hi[(size_t)N_NODES * DF];
__device__ bf16  g_h0Lo[(size_t)N_NODES * DF];
__device__ bf16  g_h1Hi[(size_t)N_NODES * DF];
__device__ bf16  g_h1Lo[(size_t)N_NODES * DF];
__device__ bf16  g_xHi[(size_t)N_NODES * DF];
__device__ bf16  g_xLo[(size_t)N_NODES * DF];
__device__ bf16  g_aggHi[(size_t)N_NODES * DF];
__device__ bf16  g_aggLo[(size_t)N_NODES * DF];
__device__ int   g_counts[N_NODES + 1];
__device__ int   g_offsets[N_NODES + 1];
__device__ int   g_cursor[N_NODES];
__device__ int   g_src_sorted[N_EDGES];
__device__ int   g_bsum[NB_SCAN];
__device__ int   g_bpre[NB_SCAN];
__device__ bf16  g_BT1[128 * KB3];   // [n][k'] n-major, k'=768
__device__ bf16  g_BT2[128 * KB3];

// ---------------- preprocessing ----------------
__global__ void zero_counts_kernel() {
    int i = blockIdx.x * blockDim.x + threadIdx.x;
    if (i <= N_NODES) g_counts[i] = 0;
}

__global__ void hist_kernel(const int* __restrict__ dst) {
    int i = blockIdx.x * blockDim.x + threadIdx.x;
    if (i < N_EDGES) atomicAdd(&g_counts[dst[i]], 1);
}

// phase 1: block-local exclusive scan + block sums
__global__ void scan1_kernel() {
    __shared__ int wsum[32];
    const int tid = threadIdx.x, lane = tid & 31, wid = tid >> 5;
    int i = blockIdx.x * 1024 + tid;
    int v = (i < N_NODES) ? g_counts[i] : 0;
    int x = v;
    #pragma unroll
    for (int o = 1; o < 32; o <<= 1) {
        int y = __shfl_up_sync(0xffffffffu, x, o);
        if (lane >= o) x += y;
    }
    if (lane == 31) wsum[wid] = x;
    __syncthreads();
    if (wid == 0) {
        int w = wsum[lane];
        #pragma unroll
        for (int o = 1; o < 32; o <<= 1) {
            int y = __shfl_up_sync(0xffffffffu, w, o);
            if (lane >= o) w += y;
        }
        wsum[lane] = w;
    }
    __syncthreads();
    int incl = x + (wid > 0 ? wsum[wid - 1] : 0);
    if (i < N_NODES) g_offsets[i] = incl - v;
    if (tid == 1023) g_bsum[blockIdx.x] = incl;
}

// phase 2: scan the 49 block sums (one block, 64 threads)
__global__ void scan2_kernel() {
    __shared__ int w0sum;
    const int tid = threadIdx.x, lane = tid & 31, wid = tid >> 5;
    int v = (tid < NB_SCAN) ? g_bsum[tid] : 0;
    int x = v;
    #pragma unroll
    for (int o = 1; o < 32; o <<= 1) {
        int y = __shfl_up_sync(0xffffffffu, x, o);
        if (lane >= o) x += y;
    }
    if (wid == 0 && lane == 31) w0sum = x;
    __syncthreads();
    int incl = x + (wid ? w0sum : 0);
    if (tid < NB_SCAN) g_bpre[tid] = incl - v;
    if (tid == NB_SCAN - 1) g_offsets[N_NODES] = incl;
}

// phase 3: add block prefixes, init cursors
__global__ void scan3_kernel() {
    int i = blockIdx.x * blockDim.x + threadIdx.x;
    if (i < N_NODES) {
        int o = g_offsets[i] + g_bpre[i >> 10];
        g_offsets[i] = o;
        g_cursor[i]  = o;
    }
}

__global__ void scatter_kernel(const int* __restrict__ src, const int* __restrict__ dst) {
    int i = blockIdx.x * blockDim.x + threadIdx.x;
    if (i < N_EDGES) {
        int d = dst[i];
        int p = atomicAdd(&g_cursor[d], 1);
        g_src_sorted[p] = src[i];
    }
}

// build BT[n][k'] for both layers: k'<256 -> hi, <512 -> hi, <768 -> lo
__global__ void buildBT_kernel(const float* __restrict__ W1, const float* __restrict__ R1,
                               const float* __restrict__ W2, const float* __restrict__ R2) {
    int i = blockIdx.x * blockDim.x + threadIdx.x;
    if (i >= 128 * KB3) return;
    int n = i / KB3, k = i % KB3;
    int seg = k >> 8, kb = k & 255;
    float w1, w2;
    if (kb < 128) { w1 = W1[kb * DF + n];          w2 = W2[kb * DF + n]; }
    else          { w1 = R1[(kb - 128) * DF + n];  w2 = R2[(kb - 128) * DF + n]; }
    bf16 h1 = __float2bfloat16_rn(w1);
    bf16 h2 = __float2bfloat16_rn(w2);
    g_BT1[i] = (seg == 2) ? __float2bfloat16_rn(w1 - __bfloat162float(h1)) : h1;
    g_BT2[i] = (seg == 2) ? __float2bfloat16_rn(w2 - __bfloat162float(h2)) : h2;
}

// convert input x to hi/lo bf16
__global__ void convx_kernel(const float* __restrict__ x) {
    int i = blockIdx.x * blockDim.x + threadIdx.x;
    if (i < N_NODES * DF) {
        float v = x[i];
        bf16 h = __float2bfloat16_rn(v);
        g_xHi[i] = h;
        g_xLo[i] = __float2bfloat16_rn(v - __bfloat162float(h));
    }
}

// ---------------- aggregation: one warp per node, CSR max-reduce ----------------
__global__ void agg_kernel(const float* __restrict__ h) {
    const int gw   = (blockIdx.x * blockDim.x + threadIdx.x) >> 5;
    const int lane = threadIdx.x & 31;
    if (gw >= N_NODES) return;
    const int beg = g_offsets[gw];
    const int end = g_offsets[gw + 1];

    float4 acc;
    acc.x = acc.y = acc.z = acc.w = -INFINITY;

    for (int j = beg; j < end; j += 32) {
        int idx = 0;
        if (j + lane < end) idx = g_src_sorted[j + lane];
        int cnt = end - j;
        if (cnt > 32) cnt = 32;
        int i = 0;
        for (; i + 4 <= cnt; i += 4) {
            int s0 = __shfl_sync(0xffffffffu, idx, i + 0);
            int s1 = __shfl_sync(0xffffffffu, idx, i + 1);
            int s2 = __shfl_sync(0xffffffffu, idx, i + 2);
            int s3 = __shfl_sync(0xffffffffu, idx, i + 3);
            float4 v0 = ((const float4*)(h + (size_t)s0 * DF))[lane];
            float4 v1 = ((const float4*)(h + (size_t)s1 * DF))[lane];
            float4 v2 = ((const float4*)(h + (size_t)s2 * DF))[lane];
            float4 v3 = ((const float4*)(h + (size_t)s3 * DF))[lane];
            v0.x = fmaxf(v0.x, v1.x); v0.y = fmaxf(v0.y, v1.y);
            v0.z = fmaxf(v0.z, v1.z); v0.w = fmaxf(v0.w, v1.w);
            v2.x = fmaxf(v2.x, v3.x); v2.y = fmaxf(v2.y, v3.y);
            v2.z = fmaxf(v2.z, v3.z); v2.w = fmaxf(v2.w, v3.w);
            acc.x = fmaxf(acc.x, fmaxf(v0.x, v2.x));
            acc.y = fmaxf(acc.y, fmaxf(v0.y, v2.y));
            acc.z = fmaxf(acc.z, fmaxf(v0.z, v2.z));
            acc.w = fmaxf(acc.w, fmaxf(v0.w, v2.w));
        }
        for (; i < cnt; i++) {
            int s = __shfl_sync(0xffffffffu, idx, i);
            float4 v = ((const float4*)(h + (size_t)s * DF))[lane];
            acc.x = fmaxf(acc.x, v.x); acc.y = fmaxf(acc.y, v.y);
            acc.z = fmaxf(acc.z, v.z); acc.w = fmaxf(acc.w, v.w);
        }
    }
    if (beg == end) { acc.x = acc.y = acc.z = acc.w = 0.0f; }

    // split into hi/lo bf16 (feeds the tensor-core GEMM)
    float vs[4] = {acc.x, acc.y, acc.z, acc.w};
    ushort4 hi4, lo4;
    unsigned short* hp = (unsigned short*)&hi4;
    unsigned short* lp = (unsigned short*)&lo4;
    #pragma unroll
    for (int q = 0; q < 4; q++) {
        bf16 h16 = __float2bfloat16_rn(vs[q]);
        bf16 l16 = __float2bfloat16_rn(vs[q] - __bfloat162float(h16));
        hp[q] = *(unsigned short*)&h16;
        lp[q] = *(unsigned short*)&l16;
    }
    ((ushort4*)(g_aggHi + (size_t)gw * DF))[lane] = hi4;
    ((ushort4*)(g_aggLo + (size_t)gw * DF))[lane] = lo4;
}

// ---------------- tensor-core GEMM ----------------
// out[m][n] = relu( A'[m][0:768] @ BT[n][0:768] + bias[n] )
// A' k-blocks: [0,256)=hi[agg|x], [256,512)=lo[agg|x], [512,768)=hi[agg|x]
#define BK 32
#define PADK 40

__global__ __launch_bounds__(256, 2)
void gemm_kernel(const bf16* __restrict__ aggHi, const bf16* __restrict__ aggLo,
                 const bf16* __restrict__ xHi,  const bf16* __restrict__ xLo,
                 const bf16* __restrict__ BT,   const float* __restrict__ bias,
                 float* __restrict__ out, bf16* __restrict__ oHi, bf16* __restrict__ oLo) {
    __shared__ bf16 As[2][128][PADK];
    __shared__ bf16 Bs[2][128][PADK];

    const int tid = threadIdx.x;
    const int mb  = blockIdx.x * 128;

    auto issue = [&](int t, int buf) {
        int kt  = t * BK;
        int seg = kt >> 8;
        int kb  = kt & 255;
        const bf16* srcA;
        int colb;
        if (kb < 128) { srcA = (seg == 1) ? aggLo : aggHi; colb = kb; }
        else          { srcA = (seg == 1) ? xLo  : xHi;    colb = kb - 128; }
        #pragma unroll
        for (int it = 0; it < 2; it++) {
            int c = tid + it * 256;
            int row = c >> 2, part = c & 3;
            {   // A (zero-fill rows beyond N_NODES)
                int grow = mb + row;
                int gr   = (grow < N_NODES) ? grow : 0;
                int sz   = (grow < N_NODES) ? 16 : 0;
                const bf16* src = srcA + (size_t)gr * DF + colb + part * 8;
                unsigned int da = (unsigned int)__cvta_generic_to_shared(&As[buf][row][part * 8]);
                asm volatile("cp.async.cg.shared.global [%0], [%1], 16, %2;\n"
                             :: "r"(da), "l"(src), "r"(sz));
            }
            {   // B
                const bf16* src = BT + (size_t)row * KB3 + kt + part * 8;
                unsigned int da = (unsigned int)__cvta_generic_to_shared(&Bs[buf][row][part * 8]);
                asm volatile("cp.async.cg.shared.global [%0], [%1], 16;\n"
                             :: "r"(da), "l"(src));
            }
        }
        asm volatile("cp.async.commit_group;\n" ::: "memory");
    };

    const int wid = tid >> 5, lane = tid & 31;
    const int mBase = (wid >> 2) * 64;   // 2 warps in m
    const int nBase = (wid & 3) * 32;    // 4 warps in n

    float acc[4][4][4];
    #pragma unroll
    for (int a = 0; a < 4; a++)
        #pragma unroll
        for (int b = 0; b < 4; b++)
            #pragma unroll
            for (int c = 0; c < 4; c++) acc[a][b][c] = 0.f;

    unsigned int aOff = (unsigned int)__cvta_generic_to_shared(
        &As[0][mBase + (lane & 15)][8 * (lane >> 4)]);
    int r16 = lane & 15;
    unsigned int bOff = (unsigned int)__cvta_generic_to_shared(
        &Bs[0][nBase + (r16 & 7)][8 * (r16 >> 3)]);
    const unsigned int bufStride = 128 * PADK * 2;

    issue(0, 0);
    const int NT = KB3 / BK;  // 24
    for (int t = 0; t < NT; t++) {
        asm volatile("cp.async.wait_group 0;\n" ::: "memory");
        __syncthreads();
        if (t + 1 < NT) issue(t + 1, (t + 1) & 1);
        int buf = t & 1;
        unsigned int aB = aOff + buf * bufStride;
        unsigned int bB = bOff + buf * bufStride;
        #pragma unroll
        for (int ks = 0; ks < 2; ks++) {
            unsigned int af[4][4], bfr[4][2];
            #pragma unroll
            for (int mt = 0; mt < 4; mt++) {
                unsigned int addr = aB + mt * (16 * PADK * 2) + ks * 32;
                asm volatile("ldmatrix.sync.aligned.m8n8.x4.shared.b16 {%0,%1,%2,%3}, [%4];\n"
                    : "=r"(af[mt][0]), "=r"(af[mt][1]), "=r"(af[mt][2]), "=r"(af[mt][3])
                    : "r"(addr));
            }
            #pragma unroll
            for (int nt = 0; nt < 4; nt++) {
                unsigned int addr = bB + nt * (8 * PADK * 2) + ks * 32;
                asm volatile("ldmatrix.sync.aligned.m8n8.x2.shared.b16 {%0,%1}, [%2];\n"
                    : "=r"(bfr[nt][0]), "=r"(bfr[nt][1]) : "r"(addr));
            }
            #pragma unroll
            for (int mt = 0; mt < 4; mt++)
                #pragma unroll
                for (int nt = 0; nt < 4; nt++)
                    asm volatile(
                        "mma.sync.aligned.m16n8k16.row.col.f32.bf16.bf16.f32 "
                        "{%0,%1,%2,%3}, {%4,%5,%6,%7}, {%8,%9}, {%0,%1,%2,%3};\n"
                        : "+f"(acc[mt][nt][0]), "+f"(acc[mt][nt][1]),
                          "+f"(acc[mt][nt][2]), "+f"(acc[mt][nt][3])
                        : "r"(af[mt][0]), "r"(af[mt][1]), "r"(af[mt][2]), "r"(af[mt][3]),
                          "r"(bfr[nt][0]), "r"(bfr[nt][1]));
        }
    }

    // epilogue: bias + relu; write fp32 h and (optionally) hi/lo bf16
    float2 bv[4];
    #pragma unroll
    for (int nt = 0; nt < 4; nt++) {
        int col = nBase + nt * 8 + (lane & 3) * 2;
        bv[nt].x = bias[col];
        bv[nt].y = bias[col + 1];
    }
    #pragma unroll
    for (int mt = 0; mt < 4; mt++) {
        #pragma unroll
        for (int half = 0; half < 2; half++) {
            int row = mb + mBase + mt * 16 + (lane >> 2) + half * 8;
            if (row >= N_NODES) continue;
            #pragma unroll
            for (int nt = 0; nt < 4; nt++) {
                int col = nBase + nt * 8 + (lane & 3) * 2;
                float v0 = fmaxf(acc[mt][nt][half * 2 + 0] + bv[nt].x, 0.f);
                float v1 = fmaxf(acc[mt][nt][half * 2 + 1] + bv[nt].y, 0.f);
                *(float2*)(out + (size_t)row * DF + col) = make_float2(v0, v1);
                if (oHi != nullptr) {
                    bf16 h0 = __float2bfloat16_rn(v0);
                    bf16 h1 = __float2bfloat16_rn(v1);
                    __nv_bfloat162 hp; hp.x = h0; hp.y = h1;
                    *(__nv_bfloat162*)(oHi + (size_t)row * DF + col) = hp;
                    __nv_bfloat162 lp;
                    lp.x = __float2bfloat16_rn(v0 - __bfloat162float(h0));
                    lp.y = __float2bfloat16_rn(v1 - __bfloat162float(h1));
                    *(__nv_bfloat162*)(oLo + (size_t)row * DF + col) = lp;
                }
            }
        }
    }
}

// ---------------- launch ----------------
extern "C" void kernel_launch(void* const* d_in, const int* in_sizes, int n_in,
                              void* d_out, int out_size) {
    const float* x  = (const float*)d_in[0];
    const int*   ei = (const int*)d_in[1];
    const float* W1 = (const float*)d_in[2];
    const float* b1 = (const float*)d_in[3];
    const float* R1 = (const float*)d_in[4];
    const float* W2 = (const float*)d_in[5];
    const float* b2 = (const float*)d_in[6];
    const float* R2 = (const float*)d_in[7];
    float* out = (float*)d_out;

    const int* src = ei;
    const int* dst = ei + N_EDGES;

    float *p_h0, *p_h1;
    bf16 *p_h0Hi, *p_h0Lo, *p_h1Hi, *p_h1Lo, *p_xHi, *p_xLo, *p_aggHi, *p_aggLo, *p_BT1, *p_BT2;
    cudaGetSymbolAddress((void**)&p_h0,    g_h0);
    cudaGetSymbolAddress((void**)&p_h1,    g_h1);
    cudaGetSymbolAddress((void**)&p_h0Hi,  g_h0Hi);
    cudaGetSymbolAddress((void**)&p_h0Lo,  g_h0Lo);
    cudaGetSymbolAddress((void**)&p_h1Hi,  g_h1Hi);
    cudaGetSymbolAddress((void**)&p_h1Lo,  g_h1Lo);
    cudaGetSymbolAddress((void**)&p_xHi,   g_xHi);
    cudaGetSymbolAddress((void**)&p_xLo,   g_xLo);
    cudaGetSymbolAddress((void**)&p_aggHi, g_aggHi);
    cudaGetSymbolAddress((void**)&p_aggLo, g_aggLo);
    cudaGetSymbolAddress((void**)&p_BT1,   g_BT1);
    cudaGetSymbolAddress((void**)&p_BT2,   g_BT2);

    // preprocessing
    zero_counts_kernel<<<(N_NODES + 256) / 256, 256>>>();
    hist_kernel<<<(N_EDGES + 255) / 256, 256>>>(dst);
    scan1_kernel<<<NB_SCAN, 1024>>>();
    scan2_kernel<<<1, 64>>>();
    scan3_kernel<<<(N_NODES + 1023) / 1024, 1024>>>();
    scatter_kernel<<<(N_EDGES + 255) / 256, 256>>>(src, dst);
    buildBT_kernel<<<(128 * KB3 + 255) / 256, 256>>>(W1, R1, W2, R2);
    convx_kernel<<<(N_NODES * DF + 255) / 256, 256>>>(x);

    const int aggBlocks  = (N_NODES * 32 + 255) / 256;
    const int gemmBlocks = (N_NODES + 127) / 128;

    // layer 1: agg(x), A=[agg|x] -> h0
    agg_kernel<<<aggBlocks, 256>>>(x);
    gemm_kernel<<<gemmBlocks, 256>>>(p_aggHi, p_aggLo, p_xHi, p_xLo, p_BT1, b1,
                                     p_h0, p_h0Hi, p_h0Lo);
    // layer 2: h0 -> h1
    agg_kernel<<<aggBlocks, 256>>>(p_h0);
    gemm_kernel<<<gemmBlocks, 256>>>(p_aggHi, p_aggLo, p_h0Hi, p_h0Lo, p_BT2, b2,
                                     p_h1, p_h1Hi, p_h1Lo);
    // layer 3: h1 -> h0
    agg_kernel<<<aggBlocks, 256>>>(p_h1);
    gemm_kernel<<<gemmBlocks, 256>>>(p_aggHi, p_aggLo, p_h1Hi, p_h1Lo, p_BT2, b2,
                                     p_h0, p_h0Hi, p_h0Lo);
    // layer 4: h0 -> out
    agg_kernel<<<aggBlocks, 256>>>(p_h0);
    gemm_kernel<<<gemmBlocks, 256>>>(p_aggHi, p_aggLo, p_h0Hi, p_h0Lo, p_BT2, b2,
                                     out, nullptr, nullptr);
}